// round 1
// baseline (speedup 1.0000x reference)
#include <cuda_runtime.h>
#include <math.h>

// Problem constants (fixed by the dataset)
#define NN 50000
#define FF 128
#define EE 800000
#define CC 10

// ---------------- scratch (static device globals; no allocation) ----------
__device__ float g_W1e[FF * FF];
__device__ float g_W2e[FF * FF];
__device__ float g_deg[NN];
__device__ float g_dinv[NN];
__device__ float g_xw[NN * FF];   // buffer A
__device__ float g_agg[NN * FF];  // buffer B

// ---------------- GRU weight evolution ------------------------------------
// W' = GRUcell(x=W0, h=W0). One block per output row m (128 blocks per weight),
// 128 threads: thread f computes W'[m,f] via 6 length-128 dot products.
__global__ void gru_kernel(const float* __restrict__ W0,
                           const float* __restrict__ wih,
                           const float* __restrict__ whh,
                           const float* __restrict__ bih,
                           const float* __restrict__ bhh,
                           float* __restrict__ Wout) {
    int m = blockIdx.x;
    int f = threadIdx.x;
    __shared__ float sW[FF];
    sW[f] = W0[m * FF + f];
    __syncthreads();

    const float* wr = wih + f * FF;
    const float* wz = wih + (f + FF) * FF;
    const float* wn = wih + (f + 2 * FF) * FF;
    const float* vr = whh + f * FF;
    const float* vz = whh + (f + FF) * FF;
    const float* vn = whh + (f + 2 * FF) * FF;

    float ir = 0.f, iz = 0.f, in_ = 0.f, hr = 0.f, hz = 0.f, hn = 0.f;
#pragma unroll 8
    for (int k = 0; k < FF; k++) {
        float a = sW[k];
        ir += a * wr[k]; iz += a * wz[k]; in_ += a * wn[k];
        hr += a * vr[k]; hz += a * vz[k]; hn += a * vn[k];
    }
    ir += bih[f];          iz += bih[f + FF];     in_ += bih[f + 2 * FF];
    hr += bhh[f];          hz += bhh[f + FF];     hn += bhh[f + 2 * FF];

    float r = 1.f / (1.f + expf(-(ir + hr)));
    float z = 1.f / (1.f + expf(-(iz + hz)));
    float n = tanhf(in_ + r * hn);
    float h = sW[f];
    Wout[m * FF + f] = (1.f - z) * n + z * h;
}

// ---------------- degree / normalization ----------------------------------
__global__ void deg_init_kernel(float* __restrict__ deg, int n) {
    int i = blockIdx.x * blockDim.x + threadIdx.x;
    if (i < n) deg[i] = 1.0f;  // self-loop contributes 1
}

__global__ void deg_acc_kernel(const int* __restrict__ dst, int e,
                               float* __restrict__ deg) {
    int i = blockIdx.x * blockDim.x + threadIdx.x;
    if (i < e) atomicAdd(&deg[dst[i]], 1.0f);
}

__global__ void dinv_kernel(const float* __restrict__ deg,
                            float* __restrict__ dinv, int n) {
    int i = blockIdx.x * blockDim.x + threadIdx.x;
    if (i < n) dinv[i] = rsqrtf(deg[i]);
}

// ---------------- GEMM: C[M,128] = act(A)[M,128] @ W[128,128] --------------
// BM=64, BK=32, 256 threads, 8x4 register tile per thread.
template <bool RELU>
__global__ void __launch_bounds__(256)
gemm_nk128(const float* __restrict__ A, const float* __restrict__ W,
           float* __restrict__ C, int M) {
    __shared__ float As[64][32];
    __shared__ float Bs[32][128];
    int tid = threadIdx.x;
    int tx = tid & 31;   // column group: cols tx*4 .. tx*4+3
    int ty = tid >> 5;   // row group:    rows ty*8 .. ty*8+7
    int row0 = blockIdx.x * 64;

    float acc[8][4];
#pragma unroll
    for (int i = 0; i < 8; i++)
#pragma unroll
        for (int j = 0; j < 4; j++) acc[i][j] = 0.f;

    for (int k0 = 0; k0 < 128; k0 += 32) {
        // A tile: 64x32 floats = 512 float4 units, 2 per thread (coalesced)
#pragma unroll
        for (int v = 0; v < 2; v++) {
            int u = tid + v * 256;
            int r = u >> 3, c4 = u & 7;
            int gr = row0 + r;
            float4 val = make_float4(0.f, 0.f, 0.f, 0.f);
            if (gr < M)
                val = *(const float4*)(A + gr * 128 + k0 + c4 * 4);
            if (RELU) {
                val.x = fmaxf(val.x, 0.f); val.y = fmaxf(val.y, 0.f);
                val.z = fmaxf(val.z, 0.f); val.w = fmaxf(val.w, 0.f);
            }
            *(float4*)&As[r][c4 * 4] = val;
        }
        // B tile: 32x128 floats = 1024 float4 units, 4 per thread (coalesced)
#pragma unroll
        for (int v = 0; v < 4; v++) {
            int u = tid + v * 256;
            int r = u >> 5, c4 = u & 31;
            *(float4*)&Bs[r][c4 * 4] = *(const float4*)(W + (k0 + r) * 128 + c4 * 4);
        }
        __syncthreads();
#pragma unroll
        for (int kk = 0; kk < 32; kk++) {
            float b[4];
            *(float4*)b = *(const float4*)&Bs[kk][tx * 4];
#pragma unroll
            for (int i = 0; i < 8; i++) {
                float a = As[ty * 8 + i][kk];  // broadcast within warp
                acc[i][0] += a * b[0];
                acc[i][1] += a * b[1];
                acc[i][2] += a * b[2];
                acc[i][3] += a * b[3];
            }
        }
        __syncthreads();
    }
#pragma unroll
    for (int i = 0; i < 8; i++) {
        int gr = row0 + ty * 8 + i;
        if (gr < M) *(float4*)(C + gr * 128 + tx * 4) = *(float4*)acc[i];
    }
}

// ---------------- self-loop init: agg[i] = dinv[i]^2 * xw[i] ----------------
__global__ void selfloop_kernel(const float4* __restrict__ xw,
                                const float* __restrict__ dinv,
                                float4* __restrict__ agg, int n) {
    int i = blockIdx.x * blockDim.x + threadIdx.x;  // over n*32 float4 units
    if (i < n * 32) {
        int row = i >> 5;
        float w = dinv[row];
        w *= w;
        float4 v = xw[i];
        agg[i] = make_float4(w * v.x, w * v.y, w * v.z, w * v.w);
    }
}

// ---------------- edge scatter: agg[dst] += dinv[s]*dinv[d]*xw[src] ---------
// One warp per edge, one float4 per lane, 4 scalar atomics per lane.
__global__ void __launch_bounds__(256)
scatter_kernel(const int* __restrict__ src, const int* __restrict__ dst, int e,
               const float* __restrict__ dinv, const float4* __restrict__ xw,
               float* __restrict__ agg) {
    int gid = blockIdx.x * blockDim.x + threadIdx.x;
    int ed = gid >> 5;
    int lane = gid & 31;
    if (ed >= e) return;
    int s = __ldg(src + ed);
    int d = __ldg(dst + ed);
    float w = __ldg(dinv + s) * __ldg(dinv + d);
    float4 v = xw[s * 32 + lane];
    float* o = agg + d * 128 + lane * 4;
    atomicAdd(o + 0, w * v.x);
    atomicAdd(o + 1, w * v.y);
    atomicAdd(o + 2, w * v.z);
    atomicAdd(o + 3, w * v.w);
}

// ---------------- final: relu -> linear(10) -> log_softmax ------------------
// One warp per node row; lin_w (10x128) staged in smem.
__global__ void __launch_bounds__(256)
final_kernel(const float* __restrict__ h, const float* __restrict__ lin_w,
             const float* __restrict__ lin_b, float* __restrict__ out, int n) {
    __shared__ float sw[CC * FF];
    __shared__ float sb[CC];
    int tid = threadIdx.x;
    for (int i = tid; i < CC * FF; i += 256) sw[i] = lin_w[i];
    if (tid < CC) sb[tid] = lin_b[tid];
    __syncthreads();

    int warp = tid >> 5, lane = tid & 31;
    int r = blockIdx.x * 8 + warp;
    if (r >= n) return;

    float4 v = *(const float4*)(h + r * 128 + lane * 4);
    v.x = fmaxf(v.x, 0.f); v.y = fmaxf(v.y, 0.f);
    v.z = fmaxf(v.z, 0.f); v.w = fmaxf(v.w, 0.f);

    float logits[CC];
#pragma unroll
    for (int c = 0; c < CC; c++) {
        float4 w = *(const float4*)(sw + c * 128 + lane * 4);
        float p = v.x * w.x + v.y * w.y + v.z * w.z + v.w * w.w;
#pragma unroll
        for (int off = 16; off > 0; off >>= 1)
            p += __shfl_xor_sync(0xffffffffu, p, off);
        logits[c] = p + sb[c];
    }
    float m = logits[0];
#pragma unroll
    for (int c = 1; c < CC; c++) m = fmaxf(m, logits[c]);
    float se = 0.f;
#pragma unroll
    for (int c = 0; c < CC; c++) se += expf(logits[c] - m);
    float lse = m + logf(se);
    if (lane == 0) {
#pragma unroll
        for (int c = 0; c < CC; c++) out[r * CC + c] = logits[c] - lse;
    }
}

// ---------------- launch ----------------------------------------------------
extern "C" void kernel_launch(void* const* d_in, const int* in_sizes, int n_in,
                              void* d_out, int out_size) {
    const float* x     = (const float*)d_in[0];
    const int*   ei    = (const int*)d_in[1];
    const float* W1    = (const float*)d_in[2];
    const float* wih1  = (const float*)d_in[3];
    const float* whh1  = (const float*)d_in[4];
    const float* bih1  = (const float*)d_in[5];
    const float* bhh1  = (const float*)d_in[6];
    const float* W2    = (const float*)d_in[7];
    const float* wih2  = (const float*)d_in[8];
    const float* whh2  = (const float*)d_in[9];
    const float* bih2  = (const float*)d_in[10];
    const float* bhh2  = (const float*)d_in[11];
    const float* lin_w = (const float*)d_in[12];
    const float* lin_b = (const float*)d_in[13];
    float* out = (float*)d_out;

    int n = in_sizes[0] / FF;   // 50000
    int e = in_sizes[1] / 2;    // 800000
    const int* src = ei;
    const int* dst = ei + e;

    float *pW1e, *pW2e, *pdeg, *pdinv, *pxw, *pagg;
    cudaGetSymbolAddress((void**)&pW1e, g_W1e);
    cudaGetSymbolAddress((void**)&pW2e, g_W2e);
    cudaGetSymbolAddress((void**)&pdeg, g_deg);
    cudaGetSymbolAddress((void**)&pdinv, g_dinv);
    cudaGetSymbolAddress((void**)&pxw, g_xw);
    cudaGetSymbolAddress((void**)&pagg, g_agg);

    // 1. evolve weights
    gru_kernel<<<FF, FF>>>(W1, wih1, whh1, bih1, bhh1, pW1e);
    gru_kernel<<<FF, FF>>>(W2, wih2, whh2, bih2, bhh2, pW2e);

    // 2. degrees -> dinv
    deg_init_kernel<<<(n + 255) / 256, 256>>>(pdeg, n);
    deg_acc_kernel<<<(e + 255) / 256, 256>>>(dst, e, pdeg);
    dinv_kernel<<<(n + 255) / 256, 256>>>(pdeg, pdinv, n);

    int gemm_blocks = (n + 63) / 64;
    int sl_blocks   = (n * 32 + 255) / 256;
    long sc_threads = (long)e * 32;
    int sc_blocks   = (int)((sc_threads + 255) / 256);

    // 3. layer 1
    gemm_nk128<false><<<gemm_blocks, 256>>>(x, pW1e, pxw, n);
    selfloop_kernel<<<sl_blocks, 256>>>((const float4*)pxw, pdinv, (float4*)pagg, n);
    scatter_kernel<<<sc_blocks, 256>>>(src, dst, e, pdinv, (const float4*)pxw, pagg);

    // 4. layer 2 (relu fused into GEMM A-load)
    gemm_nk128<true><<<gemm_blocks, 256>>>(pagg, pW2e, pxw, n);
    selfloop_kernel<<<sl_blocks, 256>>>((const float4*)pxw, pdinv, (float4*)pagg, n);
    scatter_kernel<<<sc_blocks, 256>>>(src, dst, e, pdinv, (const float4*)pxw, pagg);

    // 5. relu -> linear -> log_softmax
    final_kernel<<<(n + 7) / 8, 256>>>(pagg, lin_w, lin_b, out, n);
}

// round 2
// speedup vs baseline: 1.9183x; 1.9183x over previous
#include <cuda_runtime.h>
#include <math.h>

// Problem constants (fixed by the dataset)
#define NN 50000
#define FF 128
#define EE 800000
#define CC 10

// ---------------- scratch (static device globals; no allocation) ----------
__device__ float g_W1e[FF * FF];
__device__ float g_W2e[FF * FF];
__device__ float g_dinv[NN];
__device__ int   g_count[NN];      // degree counts (excl self-loop)
__device__ int   g_rowptr[NN + 1]; // CSR row pointers (by dst)
__device__ int   g_cursor[NN];     // fill cursors
__device__ int   g_col[EE];        // CSR col = src node
__device__ float g_colw[EE];       // per-edge norm weight dinv[s]*dinv[d]
__device__ float g_xw[NN * FF];    // buffer A
__device__ float g_agg[NN * FF];   // buffer B

// ---------------- GRU weight evolution ------------------------------------
__global__ void gru_kernel(const float* __restrict__ W0,
                           const float* __restrict__ wih,
                           const float* __restrict__ whh,
                           const float* __restrict__ bih,
                           const float* __restrict__ bhh,
                           float* __restrict__ Wout) {
    int m = blockIdx.x;
    int f = threadIdx.x;
    __shared__ float sW[FF];
    sW[f] = W0[m * FF + f];
    __syncthreads();

    const float* wr = wih + f * FF;
    const float* wz = wih + (f + FF) * FF;
    const float* wn = wih + (f + 2 * FF) * FF;
    const float* vr = whh + f * FF;
    const float* vz = whh + (f + FF) * FF;
    const float* vn = whh + (f + 2 * FF) * FF;

    float ir = 0.f, iz = 0.f, in_ = 0.f, hr = 0.f, hz = 0.f, hn = 0.f;
#pragma unroll 8
    for (int k = 0; k < FF; k++) {
        float a = sW[k];
        ir += a * wr[k]; iz += a * wz[k]; in_ += a * wn[k];
        hr += a * vr[k]; hz += a * vz[k]; hn += a * vn[k];
    }
    ir += bih[f];          iz += bih[f + FF];     in_ += bih[f + 2 * FF];
    hr += bhh[f];          hz += bhh[f + FF];     hn += bhh[f + 2 * FF];

    float r = 1.f / (1.f + expf(-(ir + hr)));
    float z = 1.f / (1.f + expf(-(iz + hz)));
    float n = tanhf(in_ + r * hn);
    float h = sW[f];
    Wout[m * FF + f] = (1.f - z) * n + z * h;
}

// ---------------- CSR build -------------------------------------------------
__global__ void hist_kernel(const int* __restrict__ dst, int e,
                            int* __restrict__ count) {
    int i = blockIdx.x * blockDim.x + threadIdx.x;
    if (i < e) atomicAdd(&count[dst[i]], 1);
}

// Single-block exclusive scan over count[n] -> rowptr, cursor; also dinv.
__global__ void __launch_bounds__(1024)
scan_kernel(const int* __restrict__ count, int* __restrict__ rowptr,
            int* __restrict__ cursor, float* __restrict__ dinv, int n) {
    __shared__ int warp_sums[32];
    __shared__ int s_offset;
    int tid = threadIdx.x;
    int lane = tid & 31, wid = tid >> 5;
    if (tid == 0) s_offset = 0;
    __syncthreads();
    for (int base = 0; base < n; base += 1024) {
        int i = base + tid;
        int c = (i < n) ? count[i] : 0;
        int v = c;
#pragma unroll
        for (int off = 1; off < 32; off <<= 1) {
            int t = __shfl_up_sync(0xffffffffu, v, off);
            if (lane >= off) v += t;
        }
        if (lane == 31) warp_sums[wid] = v;
        __syncthreads();
        if (tid < 32) {
            int w = warp_sums[tid];
#pragma unroll
            for (int off = 1; off < 32; off <<= 1) {
                int t = __shfl_up_sync(0xffffffffu, w, off);
                if (tid >= off) w += t;
            }
            warp_sums[tid] = w;
        }
        __syncthreads();
        int incl = v + (wid > 0 ? warp_sums[wid - 1] : 0);
        int excl = s_offset + incl - c;
        if (i < n) {
            rowptr[i] = excl;
            cursor[i] = excl;
            dinv[i] = rsqrtf((float)(c + 1));  // +1 for self-loop
        }
        __syncthreads();
        if (tid == 0) s_offset += warp_sums[31];
        __syncthreads();
    }
    if (tid == 0) rowptr[n] = s_offset;
}

__global__ void fill_kernel(const int* __restrict__ src,
                            const int* __restrict__ dst, int e,
                            const float* __restrict__ dinv,
                            int* __restrict__ cursor,
                            int* __restrict__ col, float* __restrict__ colw) {
    int i = blockIdx.x * blockDim.x + threadIdx.x;
    if (i >= e) return;
    int s = src[i];
    int d = dst[i];
    int idx = atomicAdd(&cursor[d], 1);
    col[idx] = s;
    colw[idx] = __ldg(dinv + s) * __ldg(dinv + d);
}

// ---------------- GEMM: C[M,128] = act(A)[M,128] @ W[128,128] --------------
template <bool RELU>
__global__ void __launch_bounds__(256)
gemm_nk128(const float* __restrict__ A, const float* __restrict__ W,
           float* __restrict__ C, int M) {
    __shared__ float As[64][32];
    __shared__ float Bs[32][128];
    int tid = threadIdx.x;
    int tx = tid & 31;
    int ty = tid >> 5;
    int row0 = blockIdx.x * 64;

    float acc[8][4];
#pragma unroll
    for (int i = 0; i < 8; i++)
#pragma unroll
        for (int j = 0; j < 4; j++) acc[i][j] = 0.f;

    for (int k0 = 0; k0 < 128; k0 += 32) {
#pragma unroll
        for (int v = 0; v < 2; v++) {
            int u = tid + v * 256;
            int r = u >> 3, c4 = u & 7;
            int gr = row0 + r;
            float4 val = make_float4(0.f, 0.f, 0.f, 0.f);
            if (gr < M)
                val = *(const float4*)(A + gr * 128 + k0 + c4 * 4);
            if (RELU) {
                val.x = fmaxf(val.x, 0.f); val.y = fmaxf(val.y, 0.f);
                val.z = fmaxf(val.z, 0.f); val.w = fmaxf(val.w, 0.f);
            }
            *(float4*)&As[r][c4 * 4] = val;
        }
#pragma unroll
        for (int v = 0; v < 4; v++) {
            int u = tid + v * 256;
            int r = u >> 5, c4 = u & 31;
            *(float4*)&Bs[r][c4 * 4] = *(const float4*)(W + (k0 + r) * 128 + c4 * 4);
        }
        __syncthreads();
#pragma unroll
        for (int kk = 0; kk < 32; kk++) {
            float b[4];
            *(float4*)b = *(const float4*)&Bs[kk][tx * 4];
#pragma unroll
            for (int i = 0; i < 8; i++) {
                float a = As[ty * 8 + i][kk];
                acc[i][0] += a * b[0];
                acc[i][1] += a * b[1];
                acc[i][2] += a * b[2];
                acc[i][3] += a * b[3];
            }
        }
        __syncthreads();
    }
#pragma unroll
    for (int i = 0; i < 8; i++) {
        int gr = row0 + ty * 8 + i;
        if (gr < M) *(float4*)(C + gr * 128 + tx * 4) = *(float4*)acc[i];
    }
}

// ---------------- gather: agg[d] = dinv[d]^2*xw[d] + sum_e w_e * xw[col_e] --
// One warp per dst node; lane owns one float4 of the 128-float row.
__global__ void __launch_bounds__(256)
gather_kernel(const int* __restrict__ rowptr, const int* __restrict__ col,
              const float* __restrict__ colw, const float* __restrict__ dinv,
              const float4* __restrict__ xw, float4* __restrict__ agg, int n) {
    int warp = (blockIdx.x * blockDim.x + threadIdx.x) >> 5;
    int lane = threadIdx.x & 31;
    if (warp >= n) return;
    int beg = __ldg(rowptr + warp);
    int end = __ldg(rowptr + warp + 1);
    float di = __ldg(dinv + warp);
    float wl = di * di;
    float4 v = xw[warp * 32 + lane];
    float4 acc = make_float4(wl * v.x, wl * v.y, wl * v.z, wl * v.w);

    int e = beg;
    // 4-way unrolled main loop for memory-level parallelism
    for (; e + 4 <= end; e += 4) {
        int s0 = __ldg(col + e + 0), s1 = __ldg(col + e + 1);
        int s2 = __ldg(col + e + 2), s3 = __ldg(col + e + 3);
        float w0 = __ldg(colw + e + 0), w1 = __ldg(colw + e + 1);
        float w2 = __ldg(colw + e + 2), w3 = __ldg(colw + e + 3);
        float4 a0 = xw[s0 * 32 + lane];
        float4 a1 = xw[s1 * 32 + lane];
        float4 a2 = xw[s2 * 32 + lane];
        float4 a3 = xw[s3 * 32 + lane];
        acc.x += w0 * a0.x + w1 * a1.x + w2 * a2.x + w3 * a3.x;
        acc.y += w0 * a0.y + w1 * a1.y + w2 * a2.y + w3 * a3.y;
        acc.z += w0 * a0.z + w1 * a1.z + w2 * a2.z + w3 * a3.z;
        acc.w += w0 * a0.w + w1 * a1.w + w2 * a2.w + w3 * a3.w;
    }
    for (; e < end; e++) {
        int s0 = __ldg(col + e);
        float w0 = __ldg(colw + e);
        float4 a0 = xw[s0 * 32 + lane];
        acc.x += w0 * a0.x; acc.y += w0 * a0.y;
        acc.z += w0 * a0.z; acc.w += w0 * a0.w;
    }
    agg[warp * 32 + lane] = acc;
}

// ---------------- final: relu -> linear(10) -> log_softmax ------------------
__global__ void __launch_bounds__(256)
final_kernel(const float* __restrict__ h, const float* __restrict__ lin_w,
             const float* __restrict__ lin_b, float* __restrict__ out, int n) {
    __shared__ float sw[CC * FF];
    __shared__ float sb[CC];
    int tid = threadIdx.x;
    for (int i = tid; i < CC * FF; i += 256) sw[i] = lin_w[i];
    if (tid < CC) sb[tid] = lin_b[tid];
    __syncthreads();

    int warp = tid >> 5, lane = tid & 31;
    int r = blockIdx.x * 8 + warp;
    if (r >= n) return;

    float4 v = *(const float4*)(h + r * 128 + lane * 4);
    v.x = fmaxf(v.x, 0.f); v.y = fmaxf(v.y, 0.f);
    v.z = fmaxf(v.z, 0.f); v.w = fmaxf(v.w, 0.f);

    float logits[CC];
#pragma unroll
    for (int c = 0; c < CC; c++) {
        float4 w = *(const float4*)(sw + c * 128 + lane * 4);
        float p = v.x * w.x + v.y * w.y + v.z * w.z + v.w * w.w;
#pragma unroll
        for (int off = 16; off > 0; off >>= 1)
            p += __shfl_xor_sync(0xffffffffu, p, off);
        logits[c] = p + sb[c];
    }
    float m = logits[0];
#pragma unroll
    for (int c = 1; c < CC; c++) m = fmaxf(m, logits[c]);
    float se = 0.f;
#pragma unroll
    for (int c = 0; c < CC; c++) se += expf(logits[c] - m);
    float lse = m + logf(se);
    if (lane == 0) {
#pragma unroll
        for (int c = 0; c < CC; c++) out[r * CC + c] = logits[c] - lse;
    }
}

// ---------------- launch ----------------------------------------------------
extern "C" void kernel_launch(void* const* d_in, const int* in_sizes, int n_in,
                              void* d_out, int out_size) {
    const float* x     = (const float*)d_in[0];
    const int*   ei    = (const int*)d_in[1];
    const float* W1    = (const float*)d_in[2];
    const float* wih1  = (const float*)d_in[3];
    const float* whh1  = (const float*)d_in[4];
    const float* bih1  = (const float*)d_in[5];
    const float* bhh1  = (const float*)d_in[6];
    const float* W2    = (const float*)d_in[7];
    const float* wih2  = (const float*)d_in[8];
    const float* whh2  = (const float*)d_in[9];
    const float* bih2  = (const float*)d_in[10];
    const float* bhh2  = (const float*)d_in[11];
    const float* lin_w = (const float*)d_in[12];
    const float* lin_b = (const float*)d_in[13];
    float* out = (float*)d_out;

    int n = in_sizes[0] / FF;   // 50000
    int e = in_sizes[1] / 2;    // 800000
    const int* src = ei;
    const int* dst = ei + e;

    float *pW1e, *pW2e, *pdinv, *pxw, *pagg, *pcolw;
    int *pcount, *prowptr, *pcursor, *pcol;
    cudaGetSymbolAddress((void**)&pW1e, g_W1e);
    cudaGetSymbolAddress((void**)&pW2e, g_W2e);
    cudaGetSymbolAddress((void**)&pdinv, g_dinv);
    cudaGetSymbolAddress((void**)&pcount, g_count);
    cudaGetSymbolAddress((void**)&prowptr, g_rowptr);
    cudaGetSymbolAddress((void**)&pcursor, g_cursor);
    cudaGetSymbolAddress((void**)&pcol, g_col);
    cudaGetSymbolAddress((void**)&pcolw, g_colw);
    cudaGetSymbolAddress((void**)&pxw, g_xw);
    cudaGetSymbolAddress((void**)&pagg, g_agg);

    // 1. evolve weights (independent of everything else)
    gru_kernel<<<FF, FF>>>(W1, wih1, whh1, bih1, bhh1, pW1e);
    gru_kernel<<<FF, FF>>>(W2, wih2, whh2, bih2, bhh2, pW2e);

    // 2. CSR build: histogram -> scan (+dinv) -> fill
    cudaMemsetAsync(pcount, 0, n * sizeof(int));
    hist_kernel<<<(e + 255) / 256, 256>>>(dst, e, pcount);
    scan_kernel<<<1, 1024>>>(pcount, prowptr, pcursor, pdinv, n);
    fill_kernel<<<(e + 255) / 256, 256>>>(src, dst, e, pdinv, pcursor, pcol, pcolw);

    int gemm_blocks = (n + 63) / 64;
    int ga_blocks   = (n * 32 + 255) / 256;  // warp per node

    // 3. layer 1
    gemm_nk128<false><<<gemm_blocks, 256>>>(x, pW1e, pxw, n);
    gather_kernel<<<ga_blocks, 256>>>(prowptr, pcol, pcolw, pdinv,
                                      (const float4*)pxw, (float4*)pagg, n);

    // 4. layer 2 (relu fused into GEMM A-load)
    gemm_nk128<true><<<gemm_blocks, 256>>>(pagg, pW2e, pxw, n);
    gather_kernel<<<ga_blocks, 256>>>(prowptr, pcol, pcolw, pdinv,
                                      (const float4*)pxw, (float4*)pagg, n);

    // 5. relu -> linear -> log_softmax
    final_kernel<<<(n + 7) / 8, 256>>>(pagg, lin_w, lin_b, out, n);
}

// round 3
// speedup vs baseline: 2.1287x; 1.1097x over previous
#include <cuda_runtime.h>
#include <math.h>

// Problem constants (fixed by the dataset)
#define NN 50000
#define FF 128
#define EE 800000
#define CC 10

#define SCAN_B 1024
#define SCAN_NB ((NN + SCAN_B - 1) / SCAN_B)   // 49

// ---------------- scratch (static device globals; no allocation) ----------
__device__ float g_W1e[FF * FF];
__device__ float g_W2e[FF * FF];
__device__ float g_dinv[NN];
__device__ int   g_count[NN];        // degree counts (excl self-loop)
__device__ int   g_rowptr[NN + 1];   // CSR row pointers (by dst)
__device__ int   g_cursor[NN];       // fill cursors
__device__ int   g_bsum[SCAN_NB];    // per-block scan sums
__device__ int   g_boff[SCAN_NB];    // per-block scan offsets
__device__ int   g_col[EE];          // CSR col = src node
__device__ float g_colw[EE];         // per-edge norm weight dinv[s]*dinv[d]
__device__ float g_xw[NN * FF];      // buffer A
__device__ float g_agg[NN * FF];     // buffer B

// ---------------- GRU weight evolution ------------------------------------
__global__ void gru_kernel(const float* __restrict__ W0,
                           const float* __restrict__ wih,
                           const float* __restrict__ whh,
                           const float* __restrict__ bih,
                           const float* __restrict__ bhh,
                           float* __restrict__ Wout) {
    int m = blockIdx.x;
    int f = threadIdx.x;
    __shared__ float sW[FF];
    sW[f] = W0[m * FF + f];
    __syncthreads();

    const float* wr = wih + f * FF;
    const float* wz = wih + (f + FF) * FF;
    const float* wn = wih + (f + 2 * FF) * FF;
    const float* vr = whh + f * FF;
    const float* vz = whh + (f + FF) * FF;
    const float* vn = whh + (f + 2 * FF) * FF;

    float ir = 0.f, iz = 0.f, in_ = 0.f, hr = 0.f, hz = 0.f, hn = 0.f;
#pragma unroll 8
    for (int k = 0; k < FF; k++) {
        float a = sW[k];
        ir += a * wr[k]; iz += a * wz[k]; in_ += a * wn[k];
        hr += a * vr[k]; hz += a * vz[k]; hn += a * vn[k];
    }
    ir += bih[f];          iz += bih[f + FF];     in_ += bih[f + 2 * FF];
    hr += bhh[f];          hz += bhh[f + FF];     hn += bhh[f + 2 * FF];

    float r = 1.f / (1.f + expf(-(ir + hr)));
    float z = 1.f / (1.f + expf(-(iz + hz)));
    float n = tanhf(in_ + r * hn);
    float h = sW[f];
    Wout[m * FF + f] = (1.f - z) * n + z * h;
}

// ---------------- CSR build -------------------------------------------------
__global__ void hist_kernel(const int* __restrict__ dst, int e,
                            int* __restrict__ count) {
    int i = blockIdx.x * blockDim.x + threadIdx.x;
    if (i < e) atomicAdd(&count[dst[i]], 1);
}

// Pass 1: per-block exclusive scan of count -> rowptr (partial), bsum[b].
__global__ void __launch_bounds__(SCAN_B)
scan_blocks_kernel(const int* __restrict__ count, int* __restrict__ rowptr,
                   int* __restrict__ bsum, int n) {
    __shared__ int warp_sums[32];
    int tid = threadIdx.x;
    int lane = tid & 31, wid = tid >> 5;
    int i = blockIdx.x * SCAN_B + tid;
    int c = (i < n) ? count[i] : 0;
    int v = c;
#pragma unroll
    for (int off = 1; off < 32; off <<= 1) {
        int t = __shfl_up_sync(0xffffffffu, v, off);
        if (lane >= off) v += t;
    }
    if (lane == 31) warp_sums[wid] = v;
    __syncthreads();
    if (tid < 32) {
        int w = warp_sums[tid];
#pragma unroll
        for (int off = 1; off < 32; off <<= 1) {
            int t = __shfl_up_sync(0xffffffffu, w, off);
            if (tid >= off) w += t;
        }
        warp_sums[tid] = w;
    }
    __syncthreads();
    int incl = v + (wid > 0 ? warp_sums[wid - 1] : 0);
    if (i < n) rowptr[i] = incl - c;            // block-local exclusive
    if (tid == SCAN_B - 1) bsum[blockIdx.x] = incl;
}

// Pass 2: single small block scans the 49 block sums (exclusive) -> boff,
// and writes the grand total to rowptr[n].
__global__ void scan_tops_kernel(const int* __restrict__ bsum,
                                 int* __restrict__ boff,
                                 int* __restrict__ rowptr, int n, int nb) {
    int tid = threadIdx.x;  // 64 threads, nb <= 64
    int c = (tid < nb) ? bsum[tid] : 0;
    int v = c;
#pragma unroll
    for (int off = 1; off < 32; off <<= 1) {
        int t = __shfl_up_sync(0xffffffffu, v, off);
        if ((tid & 31) >= off) v += t;
    }
    __shared__ int w0sum;
    if (tid == 31) w0sum = v;
    __syncthreads();
    int incl = v + ((tid >= 32) ? w0sum : 0);
    if (tid < nb) boff[tid] = incl - c;
    if (tid == nb - 1) rowptr[n] = incl;
}

// Pass 3: add block offsets; write cursor and dinv.
__global__ void __launch_bounds__(SCAN_B)
scan_add_kernel(const int* __restrict__ count, const int* __restrict__ boff,
                int* __restrict__ rowptr, int* __restrict__ cursor,
                float* __restrict__ dinv, int n) {
    int i = blockIdx.x * SCAN_B + threadIdx.x;
    if (i >= n) return;
    int r = rowptr[i] + boff[blockIdx.x];
    rowptr[i] = r;
    cursor[i] = r;
    dinv[i] = rsqrtf((float)(count[i] + 1));    // +1 self-loop
}

__global__ void fill_kernel(const int* __restrict__ src,
                            const int* __restrict__ dst, int e,
                            const float* __restrict__ dinv,
                            int* __restrict__ cursor,
                            int* __restrict__ col, float* __restrict__ colw) {
    int i = blockIdx.x * blockDim.x + threadIdx.x;
    if (i >= e) return;
    int s = src[i];
    int d = dst[i];
    int idx = atomicAdd(&cursor[d], 1);
    col[idx] = s;
    colw[idx] = __ldg(dinv + s) * __ldg(dinv + d);
}

// ---------------- GEMM: C[M,128] = act(A)[M,128] @ W[128,128] --------------
template <bool RELU>
__global__ void __launch_bounds__(256)
gemm_nk128(const float* __restrict__ A, const float* __restrict__ W,
           float* __restrict__ C, int M) {
    __shared__ float As[64][32];
    __shared__ float Bs[32][128];
    int tid = threadIdx.x;
    int tx = tid & 31;
    int ty = tid >> 5;
    int row0 = blockIdx.x * 64;

    float acc[8][4];
#pragma unroll
    for (int i = 0; i < 8; i++)
#pragma unroll
        for (int j = 0; j < 4; j++) acc[i][j] = 0.f;

    for (int k0 = 0; k0 < 128; k0 += 32) {
#pragma unroll
        for (int v = 0; v < 2; v++) {
            int u = tid + v * 256;
            int r = u >> 3, c4 = u & 7;
            int gr = row0 + r;
            float4 val = make_float4(0.f, 0.f, 0.f, 0.f);
            if (gr < M)
                val = *(const float4*)(A + gr * 128 + k0 + c4 * 4);
            if (RELU) {
                val.x = fmaxf(val.x, 0.f); val.y = fmaxf(val.y, 0.f);
                val.z = fmaxf(val.z, 0.f); val.w = fmaxf(val.w, 0.f);
            }
            *(float4*)&As[r][c4 * 4] = val;
        }
#pragma unroll
        for (int v = 0; v < 4; v++) {
            int u = tid + v * 256;
            int r = u >> 5, c4 = u & 31;
            *(float4*)&Bs[r][c4 * 4] = *(const float4*)(W + (k0 + r) * 128 + c4 * 4);
        }
        __syncthreads();
#pragma unroll
        for (int kk = 0; kk < 32; kk++) {
            float b[4];
            *(float4*)b = *(const float4*)&Bs[kk][tx * 4];
#pragma unroll
            for (int i = 0; i < 8; i++) {
                float a = As[ty * 8 + i][kk];
                acc[i][0] += a * b[0];
                acc[i][1] += a * b[1];
                acc[i][2] += a * b[2];
                acc[i][3] += a * b[3];
            }
        }
        __syncthreads();
    }
#pragma unroll
    for (int i = 0; i < 8; i++) {
        int gr = row0 + ty * 8 + i;
        if (gr < M) *(float4*)(C + gr * 128 + tx * 4) = *(float4*)acc[i];
    }
}

// ---------------- gather: agg[d] = dinv[d]^2*xw[d] + sum_e w_e * xw[col_e] --
__global__ void __launch_bounds__(256)
gather_kernel(const int* __restrict__ rowptr, const int* __restrict__ col,
              const float* __restrict__ colw, const float* __restrict__ dinv,
              const float4* __restrict__ xw, float4* __restrict__ agg, int n) {
    int warp = (blockIdx.x * blockDim.x + threadIdx.x) >> 5;
    int lane = threadIdx.x & 31;
    if (warp >= n) return;
    int beg = __ldg(rowptr + warp);
    int end = __ldg(rowptr + warp + 1);
    float di = __ldg(dinv + warp);
    float wl = di * di;
    float4 v = xw[warp * 32 + lane];
    float4 acc = make_float4(wl * v.x, wl * v.y, wl * v.z, wl * v.w);

    int e = beg;
    for (; e + 4 <= end; e += 4) {
        int s0 = __ldg(col + e + 0), s1 = __ldg(col + e + 1);
        int s2 = __ldg(col + e + 2), s3 = __ldg(col + e + 3);
        float w0 = __ldg(colw + e + 0), w1 = __ldg(colw + e + 1);
        float w2 = __ldg(colw + e + 2), w3 = __ldg(colw + e + 3);
        float4 a0 = xw[s0 * 32 + lane];
        float4 a1 = xw[s1 * 32 + lane];
        float4 a2 = xw[s2 * 32 + lane];
        float4 a3 = xw[s3 * 32 + lane];
        acc.x += w0 * a0.x + w1 * a1.x + w2 * a2.x + w3 * a3.x;
        acc.y += w0 * a0.y + w1 * a1.y + w2 * a2.y + w3 * a3.y;
        acc.z += w0 * a0.z + w1 * a1.z + w2 * a2.z + w3 * a3.z;
        acc.w += w0 * a0.w + w1 * a1.w + w2 * a2.w + w3 * a3.w;
    }
    for (; e < end; e++) {
        int s0 = __ldg(col + e);
        float w0 = __ldg(colw + e);
        float4 a0 = xw[s0 * 32 + lane];
        acc.x += w0 * a0.x; acc.y += w0 * a0.y;
        acc.z += w0 * a0.z; acc.w += w0 * a0.w;
    }
    agg[warp * 32 + lane] = acc;
}

// ---------------- final: relu -> linear(10) -> log_softmax ------------------
__global__ void __launch_bounds__(256)
final_kernel(const float* __restrict__ h, const float* __restrict__ lin_w,
             const float* __restrict__ lin_b, float* __restrict__ out, int n) {
    __shared__ float sw[CC * FF];
    __shared__ float sb[CC];
    int tid = threadIdx.x;
    for (int i = tid; i < CC * FF; i += 256) sw[i] = lin_w[i];
    if (tid < CC) sb[tid] = lin_b[tid];
    __syncthreads();

    int warp = tid >> 5, lane = tid & 31;
    int r = blockIdx.x * 8 + warp;
    if (r >= n) return;

    float4 v = *(const float4*)(h + r * 128 + lane * 4);
    v.x = fmaxf(v.x, 0.f); v.y = fmaxf(v.y, 0.f);
    v.z = fmaxf(v.z, 0.f); v.w = fmaxf(v.w, 0.f);

    float logits[CC];
#pragma unroll
    for (int c = 0; c < CC; c++) {
        float4 w = *(const float4*)(sw + c * 128 + lane * 4);
        float p = v.x * w.x + v.y * w.y + v.z * w.z + v.w * w.w;
#pragma unroll
        for (int off = 16; off > 0; off >>= 1)
            p += __shfl_xor_sync(0xffffffffu, p, off);
        logits[c] = p + sb[c];
    }
    float m = logits[0];
#pragma unroll
    for (int c = 1; c < CC; c++) m = fmaxf(m, logits[c]);
    float se = 0.f;
#pragma unroll
    for (int c = 0; c < CC; c++) se += expf(logits[c] - m);
    float lse = m + logf(se);
    if (lane == 0) {
#pragma unroll
        for (int c = 0; c < CC; c++) out[r * CC + c] = logits[c] - lse;
    }
}

// ---------------- launch ----------------------------------------------------
extern "C" void kernel_launch(void* const* d_in, const int* in_sizes, int n_in,
                              void* d_out, int out_size) {
    const float* x     = (const float*)d_in[0];
    const int*   ei    = (const int*)d_in[1];
    const float* W1    = (const float*)d_in[2];
    const float* wih1  = (const float*)d_in[3];
    const float* whh1  = (const float*)d_in[4];
    const float* bih1  = (const float*)d_in[5];
    const float* bhh1  = (const float*)d_in[6];
    const float* W2    = (const float*)d_in[7];
    const float* wih2  = (const float*)d_in[8];
    const float* whh2  = (const float*)d_in[9];
    const float* bih2  = (const float*)d_in[10];
    const float* bhh2  = (const float*)d_in[11];
    const float* lin_w = (const float*)d_in[12];
    const float* lin_b = (const float*)d_in[13];
    float* out = (float*)d_out;

    int n = in_sizes[0] / FF;   // 50000
    int e = in_sizes[1] / 2;    // 800000
    const int* src = ei;
    const int* dst = ei + e;

    float *pW1e, *pW2e, *pdinv, *pxw, *pagg, *pcolw;
    int *pcount, *prowptr, *pcursor, *pcol, *pbsum, *pboff;
    cudaGetSymbolAddress((void**)&pW1e, g_W1e);
    cudaGetSymbolAddress((void**)&pW2e, g_W2e);
    cudaGetSymbolAddress((void**)&pdinv, g_dinv);
    cudaGetSymbolAddress((void**)&pcount, g_count);
    cudaGetSymbolAddress((void**)&prowptr, g_rowptr);
    cudaGetSymbolAddress((void**)&pcursor, g_cursor);
    cudaGetSymbolAddress((void**)&pcol, g_col);
    cudaGetSymbolAddress((void**)&pcolw, g_colw);
    cudaGetSymbolAddress((void**)&pxw, g_xw);
    cudaGetSymbolAddress((void**)&pagg, g_agg);
    cudaGetSymbolAddress((void**)&pbsum, g_bsum);
    cudaGetSymbolAddress((void**)&pboff, g_boff);

    int nb = (n + SCAN_B - 1) / SCAN_B;  // 49

    // 1. evolve weights
    gru_kernel<<<FF, FF>>>(W1, wih1, whh1, bih1, bhh1, pW1e);
    gru_kernel<<<FF, FF>>>(W2, wih2, whh2, bih2, bhh2, pW2e);

    // 2. CSR build: histogram -> 3-pass scan -> fill
    cudaMemsetAsync(pcount, 0, n * sizeof(int));
    hist_kernel<<<(e + 255) / 256, 256>>>(dst, e, pcount);
    scan_blocks_kernel<<<nb, SCAN_B>>>(pcount, prowptr, pbsum, n);
    scan_tops_kernel<<<1, 64>>>(pbsum, pboff, prowptr, n, nb);
    scan_add_kernel<<<nb, SCAN_B>>>(pcount, pboff, prowptr, pcursor, pdinv, n);
    fill_kernel<<<(e + 255) / 256, 256>>>(src, dst, e, pdinv, pcursor, pcol, pcolw);

    int gemm_blocks = (n + 63) / 64;
    int ga_blocks   = (n * 32 + 255) / 256;

    // 3. layer 1
    gemm_nk128<false><<<gemm_blocks, 256>>>(x, pW1e, pxw, n);
    gather_kernel<<<ga_blocks, 256>>>(prowptr, pcol, pcolw, pdinv,
                                      (const float4*)pxw, (float4*)pagg, n);

    // 4. layer 2 (relu fused into GEMM A-load)
    gemm_nk128<true><<<gemm_blocks, 256>>>(pagg, pW2e, pxw, n);
    gather_kernel<<<ga_blocks, 256>>>(prowptr, pcol, pcolw, pdinv,
                                      (const float4*)pxw, (float4*)pagg, n);

    // 5. relu -> linear -> log_softmax
    final_kernel<<<(n + 7) / 8, 256>>>(pagg, lin_w, lin_b, out, n);
}